// round 1
// baseline (speedup 1.0000x reference)
#include <cuda_runtime.h>
#include <math_constants.h>

// MSAColumnGlobalAttention: B=1, s=1024, i=512, c=8, h=8
// One CTA per column i. 256 threads, 4 rows (s values) per thread.
//
// Algebraic simplification: q = mean_s(x) @ Wq.T  (reshape doesn't mix s),
// so the per-row Wq GEMM collapses to one tiny matvec per column.

#define LN_EPS 1e-5f
#define S_DIM 1024
#define I_DIM 512
#define C_DIM 8
#define H_DIM 8
#define THREADS 256
#define ROWS_PT (S_DIM / THREADS)   // 4

__device__ __forceinline__ float dot8(const float x[8], const float* __restrict__ w) {
    float s = x[0] * w[0];
#pragma unroll
    for (int j = 1; j < 8; j++) s = fmaf(x[j], w[j], s);
    return s;
}

__global__ __launch_bounds__(THREADS)
void msa_col_global_attn_kernel(
    const float* __restrict__ m,
    const float* __restrict__ ln_gamma,
    const float* __restrict__ ln_beta,
    const float* __restrict__ Wq,    // (64, 8)
    const float* __restrict__ Wk,    // (8, 8)
    const float* __restrict__ Wv,    // (8, 8)
    const float* __restrict__ Wg,    // (64, 8)
    const float* __restrict__ Wo,    // (8, 64)
    const float* __restrict__ bo,    // (8,)
    float* __restrict__ out)
{
    const int i    = blockIdx.x;          // column index 0..511
    const int tid  = threadIdx.x;
    const int lane = tid & 31;
    const int warp = tid >> 5;            // 8 warps

    __shared__ float sWq[64 * 8];
    __shared__ float sWk[64];
    __shared__ float sWv[64];
    __shared__ float sWg[64 * 8];
    __shared__ float sWoT[64 * 8];        // transposed: [idx][cout]
    __shared__ float sGamma[8], sBeta[8], sBo[8];
    __shared__ float sQ[64];              // q[h*8+c], pre-scaled
    __shared__ float sRed[8][8];          // per-warp partials
    __shared__ float sXbar[8];
    __shared__ float sHmax[8];
    __shared__ float sHrcp[8];

    // ---- stage weights into SMEM ----
    for (int j = tid; j < 512; j += THREADS) {
        sWq[j] = Wq[j];
        sWg[j] = Wg[j];
        // Wo is (8, 64) row-major: Wo[co*64 + idx] -> sWoT[idx*8 + co]
        sWoT[(j & 63) * 8 + (j >> 6)] = Wo[j];
    }
    if (tid < 64) { sWk[tid] = Wk[tid]; sWv[tid] = Wv[tid]; }
    if (tid < 8)  { sGamma[tid] = ln_gamma[tid]; sBeta[tid] = ln_beta[tid]; sBo[tid] = bo[tid]; }
    __syncthreads();

    // ---- phase 1: load + LayerNorm, accumulate column mean ----
    float x[ROWS_PT][8];
    float acc[8];
#pragma unroll
    for (int c = 0; c < 8; c++) acc[c] = 0.f;

#pragma unroll
    for (int r = 0; r < ROWS_PT; r++) {
        const int s = r * THREADS + tid;
        const float4* p = reinterpret_cast<const float4*>(m + ((size_t)s * I_DIM + i) * C_DIM);
        float4 a0 = p[0];
        float4 a1 = p[1];
        float xr[8] = {a0.x, a0.y, a0.z, a0.w, a1.x, a1.y, a1.z, a1.w};
        float mean = 0.f;
#pragma unroll
        for (int c = 0; c < 8; c++) mean += xr[c];
        mean *= 0.125f;
        float var = 0.f;
#pragma unroll
        for (int c = 0; c < 8; c++) { float d = xr[c] - mean; var = fmaf(d, d, var); }
        var *= 0.125f;
        const float rstd = rsqrtf(var + LN_EPS);
#pragma unroll
        for (int c = 0; c < 8; c++) {
            float t = (xr[c] - mean) * rstd;
            t = fmaf(t, sGamma[c], sBeta[c]);
            x[r][c] = t;
            acc[c] += t;
        }
    }

    // ---- block-reduce sum(x) over s -> xbar ----
#pragma unroll
    for (int c = 0; c < 8; c++) {
#pragma unroll
        for (int off = 16; off > 0; off >>= 1)
            acc[c] += __shfl_xor_sync(0xffffffffu, acc[c], off);
    }
    if (lane == 0) {
#pragma unroll
        for (int c = 0; c < 8; c++) sRed[warp][c] = acc[c];
    }
    __syncthreads();
    if (tid < 8) {
        float s = sRed[0][tid];
#pragma unroll
        for (int w = 1; w < 8; w++) s += sRed[w][tid];
        sXbar[tid] = s;
    }
    __syncthreads();

    // ---- q = xbar @ Wq.T, folded with 1/1024 (mean) and c^-0.5 (attn scale) ----
    if (tid < 64) {
        const float qscale = (1.f / 1024.f) * 0.35355339059327373f; // 1/sqrt(8)
        sQ[tid] = dot8(sXbar, &sWq[tid * 8]) * qscale;
    }
    __syncthreads();

    // ---- phase 3: logits a[t,h] = q . k[t], track per-h max ----
    float e[ROWS_PT][8];
    float hred[8];
#pragma unroll
    for (int h = 0; h < 8; h++) hred[h] = -1e30f;

#pragma unroll
    for (int r = 0; r < ROWS_PT; r++) {
        float k[8];
#pragma unroll
        for (int c = 0; c < 8; c++) k[c] = dot8(x[r], &sWk[c * 8]);
#pragma unroll
        for (int h = 0; h < 8; h++) {
            float a = dot8(k, &sQ[h * 8]);
            e[r][h] = a;
            hred[h] = fmaxf(hred[h], a);
        }
    }

    // ---- block-reduce max per h ----
#pragma unroll
    for (int h = 0; h < 8; h++) {
#pragma unroll
        for (int off = 16; off > 0; off >>= 1)
            hred[h] = fmaxf(hred[h], __shfl_xor_sync(0xffffffffu, hred[h], off));
    }
    if (lane == 0) {
#pragma unroll
        for (int h = 0; h < 8; h++) sRed[warp][h] = hred[h];
    }
    __syncthreads();
    if (tid < 8) {
        float s = sRed[0][tid];
#pragma unroll
        for (int w = 1; w < 8; w++) s = fmaxf(s, sRed[w][tid]);
        sHmax[tid] = s;
    }
    __syncthreads();

    // ---- exp + per-h sum ----
#pragma unroll
    for (int h = 0; h < 8; h++) hred[h] = 0.f;
#pragma unroll
    for (int r = 0; r < ROWS_PT; r++) {
#pragma unroll
        for (int h = 0; h < 8; h++) {
            float ev = __expf(e[r][h] - sHmax[h]);
            e[r][h] = ev;
            hred[h] += ev;
        }
    }
#pragma unroll
    for (int h = 0; h < 8; h++) {
#pragma unroll
        for (int off = 16; off > 0; off >>= 1)
            hred[h] += __shfl_xor_sync(0xffffffffu, hred[h], off);
    }
    if (lane == 0) {
#pragma unroll
        for (int h = 0; h < 8; h++) sRed[warp][h] = hred[h];
    }
    __syncthreads();
    if (tid < 8) {
        float s = sRed[0][tid];
#pragma unroll
        for (int w = 1; w < 8; w++) s += sRed[w][tid];
        sHrcp[tid] = __fdividef(1.f, s);
    }
    __syncthreads();

    // ---- phase 5: v, gate, Wo contraction, store ----
#pragma unroll 1
    for (int r = 0; r < ROWS_PT; r++) {
        const int s = r * THREADS + tid;

        float v[8];
#pragma unroll
        for (int c = 0; c < 8; c++) v[c] = dot8(x[r], &sWv[c * 8]);

        float w8[8];
#pragma unroll
        for (int h = 0; h < 8; h++) w8[h] = e[r][h] * sHrcp[h];

        float o[8];
#pragma unroll
        for (int co = 0; co < 8; co++) o[co] = sBo[co];

#pragma unroll 2
        for (int h = 0; h < 8; h++) {
            const float wh = w8[h];
#pragma unroll
            for (int c = 0; c < 8; c++) {
                const int idx = h * 8 + c;
                const float g   = dot8(x[r], &sWg[idx * 8]);
                const float sig = __fdividef(1.f, 1.f + __expf(-g));
                const float coef = sig * wh * v[c];
                const float* wo = &sWoT[idx * 8];
#pragma unroll
                for (int co = 0; co < 8; co++) o[co] = fmaf(wo[co], coef, o[co]);
            }
        }

        float4* po = reinterpret_cast<float4*>(out + ((size_t)s * I_DIM + i) * C_DIM);
        po[0] = make_float4(o[0], o[1], o[2], o[3]);
        po[1] = make_float4(o[4], o[5], o[6], o[7]);
    }
}

extern "C" void kernel_launch(void* const* d_in, const int* in_sizes, int n_in,
                              void* d_out, int out_size) {
    (void)in_sizes; (void)n_in; (void)out_size;
    const float* m        = (const float*)d_in[0];
    const float* ln_gamma = (const float*)d_in[1];
    const float* ln_beta  = (const float*)d_in[2];
    const float* Wq       = (const float*)d_in[3];
    const float* Wk       = (const float*)d_in[4];
    const float* Wv       = (const float*)d_in[5];
    const float* Wg       = (const float*)d_in[6];
    const float* Wo       = (const float*)d_in[7];
    const float* bo       = (const float*)d_in[8];
    float* out = (float*)d_out;

    msa_col_global_attn_kernel<<<I_DIM, THREADS>>>(
        m, ln_gamma, ln_beta, Wq, Wk, Wv, Wg, Wo, bo, out);
}

// round 2
// speedup vs baseline: 1.0370x; 1.0370x over previous
#include <cuda_runtime.h>
#include <math_constants.h>

// MSAColumnGlobalAttention: B=1, s=1024, i=512, c=8, h=8
// One CTA per column i. 512 threads, 2 rows (s values) per thread.
// Heavy loops use packed fma.rn.f32x2 (sm_100+) to halve FMA-pipe instructions.

#define LN_EPS 1e-5f
#define S_DIM 1024
#define I_DIM 512
#define THREADS 512
#define ROWS_PT (S_DIM / THREADS)   // 2
#define NWARP (THREADS / 32)        // 16

// ---- packed f32x2 helpers ----
__device__ __forceinline__ float2 fma2(float2 a, float2 b, float2 c) {
    unsigned long long ra = *reinterpret_cast<unsigned long long*>(&a);
    unsigned long long rb = *reinterpret_cast<unsigned long long*>(&b);
    unsigned long long rc = *reinterpret_cast<unsigned long long*>(&c);
    unsigned long long rd;
    asm("fma.rn.f32x2 %0, %1, %2, %3;" : "=l"(rd) : "l"(ra), "l"(rb), "l"(rc));
    return *reinterpret_cast<float2*>(&rd);
}
__device__ __forceinline__ float2 mul2(float2 a, float2 b) {
    unsigned long long ra = *reinterpret_cast<unsigned long long*>(&a);
    unsigned long long rb = *reinterpret_cast<unsigned long long*>(&b);
    unsigned long long rd;
    asm("mul.rn.f32x2 %0, %1, %2;" : "=l"(rd) : "l"(ra), "l"(rb));
    return *reinterpret_cast<float2*>(&rd);
}
__device__ __forceinline__ float2 dup(float x) { return make_float2(x, x); }

__device__ __forceinline__ float dot8(const float x[8], const float* __restrict__ w) {
    float s = x[0] * w[0];
#pragma unroll
    for (int j = 1; j < 8; j++) s = fmaf(x[j], w[j], s);
    return s;
}

__global__ __launch_bounds__(THREADS, 1)
void msa_col_global_attn_kernel(
    const float* __restrict__ m,
    const float* __restrict__ ln_gamma,
    const float* __restrict__ ln_beta,
    const float* __restrict__ Wq,    // (64, 8)
    const float* __restrict__ Wk,    // (8, 8)
    const float* __restrict__ Wv,    // (8, 8)
    const float* __restrict__ Wg,    // (64, 8)
    const float* __restrict__ Wo,    // (8, 64)
    const float* __restrict__ bo,    // (8,)
    float* __restrict__ out)
{
    const int i    = blockIdx.x;
    const int tid  = threadIdx.x;
    const int lane = tid & 31;
    const int warp = tid >> 5;

    __shared__ float  sWq[64 * 8];
    __shared__ float2 sWk2[4][8];    // [c_pair][j] = {Wk[2p][j], Wk[2p+1][j]}
    __shared__ float2 sWv2[4][8];
    __shared__ float2 sQ2[4][8];     // [h_pair][j] = {q[2p][j], q[2p+1][j]} pre-scaled
    __shared__ float2 sWg2[32][8];   // [idx_pair][j]
    __shared__ float2 sWo2[64][4];   // [idx][co_pair] = {Wo[2q][idx], Wo[2q+1][idx]}
    __shared__ float  sGamma[8], sBeta[8], sBo[8];
    __shared__ float  sRed[NWARP][8];
    __shared__ float  sXbar[8];
    __shared__ float  sHmax[8];
    __shared__ float  sHrcp[8];

    // ---- stage weights into SMEM (packed layouts) ----
    if (tid < 512) {
        const int row = tid >> 3;       // 0..63
        const int j   = tid & 7;
        sWq[tid] = Wq[tid];
        // Wg[row][j] -> sWg2[row>>1][j] component row&1
        reinterpret_cast<float*>(&sWg2[row >> 1][j])[row & 1] = Wg[tid];
        // Wo is (8,64): Wo[co*64 + idx]; tid = co*64 + idx
        const int co = tid >> 6, idx = tid & 63;
        reinterpret_cast<float*>(&sWo2[idx][co >> 1])[co & 1] = Wo[tid];
    }
    if (tid < 64) {
        const int row = tid >> 3, j = tid & 7;
        reinterpret_cast<float*>(&sWk2[row >> 1][j])[row & 1] = Wk[tid];
        reinterpret_cast<float*>(&sWv2[row >> 1][j])[row & 1] = Wv[tid];
    }
    if (tid < 8) { sGamma[tid] = ln_gamma[tid]; sBeta[tid] = ln_beta[tid]; sBo[tid] = bo[tid]; }
    __syncthreads();

    // ---- phase 1: load + LayerNorm, accumulate column sum ----
    float x[ROWS_PT][8];
    float acc[8];
#pragma unroll
    for (int c = 0; c < 8; c++) acc[c] = 0.f;

#pragma unroll
    for (int r = 0; r < ROWS_PT; r++) {
        const int s = r * THREADS + tid;
        const float4* p = reinterpret_cast<const float4*>(m + ((size_t)s * I_DIM + i) * 8);
        float4 a0 = p[0];
        float4 a1 = p[1];
        float xr[8] = {a0.x, a0.y, a0.z, a0.w, a1.x, a1.y, a1.z, a1.w};
        float mean = 0.f;
#pragma unroll
        for (int c = 0; c < 8; c++) mean += xr[c];
        mean *= 0.125f;
        float var = 0.f;
#pragma unroll
        for (int c = 0; c < 8; c++) { float d = xr[c] - mean; var = fmaf(d, d, var); }
        var *= 0.125f;
        const float rstd = rsqrtf(var + LN_EPS);
#pragma unroll
        for (int c = 0; c < 8; c++) {
            float t = (xr[c] - mean) * rstd;
            t = fmaf(t, sGamma[c], sBeta[c]);
            x[r][c] = t;
            acc[c] += t;
        }
    }

    // ---- block-reduce sum(x) over s -> xbar ----
#pragma unroll
    for (int c = 0; c < 8; c++) {
#pragma unroll
        for (int off = 16; off > 0; off >>= 1)
            acc[c] += __shfl_xor_sync(0xffffffffu, acc[c], off);
    }
    if (lane == 0) {
#pragma unroll
        for (int c = 0; c < 8; c++) sRed[warp][c] = acc[c];
    }
    __syncthreads();
    if (tid < 8) {
        float s = sRed[0][tid];
#pragma unroll
        for (int w = 1; w < NWARP; w++) s += sRed[w][tid];
        sXbar[tid] = s;
    }
    __syncthreads();

    // ---- q = xbar @ Wq.T, folded with 1/1024 (mean) and c^-0.5 ----
    if (tid < 64) {
        const float qscale = (1.f / 1024.f) * 0.35355339059327373f;
        const float val = dot8(sXbar, &sWq[tid * 8]) * qscale;
        const int h = tid >> 3, j = tid & 7;
        reinterpret_cast<float*>(&sQ2[h >> 1][j])[h & 1] = val;
    }
    __syncthreads();

    // ---- phase 3: k = x@Wk.T (packed), logits (packed over h pairs), per-h max ----
    float e[ROWS_PT][8];
    float hred[8];
#pragma unroll
    for (int h = 0; h < 8; h++) hred[h] = -1e30f;

#pragma unroll
    for (int r = 0; r < ROWS_PT; r++) {
        float2 xd[8];
#pragma unroll
        for (int j = 0; j < 8; j++) xd[j] = dup(x[r][j]);

        float k[8];
#pragma unroll
        for (int p = 0; p < 4; p++) {
            float2 a = mul2(xd[0], sWk2[p][0]);
#pragma unroll
            for (int j = 1; j < 8; j++) a = fma2(xd[j], sWk2[p][j], a);
            k[2 * p] = a.x; k[2 * p + 1] = a.y;
        }

        float2 a2[4];
#pragma unroll
        for (int p = 0; p < 4; p++) a2[p] = make_float2(0.f, 0.f);
#pragma unroll
        for (int j = 0; j < 8; j++) {
            const float2 kd = dup(k[j]);
#pragma unroll
            for (int p = 0; p < 4; p++) a2[p] = fma2(kd, sQ2[p][j], a2[p]);
        }
#pragma unroll
        for (int p = 0; p < 4; p++) {
            e[r][2 * p]     = a2[p].x;
            e[r][2 * p + 1] = a2[p].y;
            hred[2 * p]     = fmaxf(hred[2 * p],     a2[p].x);
            hred[2 * p + 1] = fmaxf(hred[2 * p + 1], a2[p].y);
        }
    }

    // ---- block-reduce max per h ----
#pragma unroll
    for (int h = 0; h < 8; h++) {
#pragma unroll
        for (int off = 16; off > 0; off >>= 1)
            hred[h] = fmaxf(hred[h], __shfl_xor_sync(0xffffffffu, hred[h], off));
    }
    if (lane == 0) {
#pragma unroll
        for (int h = 0; h < 8; h++) sRed[warp][h] = hred[h];
    }
    __syncthreads();
    if (tid < 8) {
        float s = sRed[0][tid];
#pragma unroll
        for (int w = 1; w < NWARP; w++) s = fmaxf(s, sRed[w][tid]);
        sHmax[tid] = s;
    }
    __syncthreads();

    // ---- exp + per-h sum ----
#pragma unroll
    for (int h = 0; h < 8; h++) hred[h] = 0.f;
#pragma unroll
    for (int r = 0; r < ROWS_PT; r++) {
#pragma unroll
        for (int h = 0; h < 8; h++) {
            float ev = __expf(e[r][h] - sHmax[h]);
            e[r][h] = ev;
            hred[h] += ev;
        }
    }
#pragma unroll
    for (int h = 0; h < 8; h++) {
#pragma unroll
        for (int off = 16; off > 0; off >>= 1)
            hred[h] += __shfl_xor_sync(0xffffffffu, hred[h], off);
    }
    if (lane == 0) {
#pragma unroll
        for (int h = 0; h < 8; h++) sRed[warp][h] = hred[h];
    }
    __syncthreads();
    if (tid < 8) {
        float s = sRed[0][tid];
#pragma unroll
        for (int w = 1; w < NWARP; w++) s += sRed[w][tid];
        sHrcp[tid] = __fdividef(1.f, s);
    }
    __syncthreads();

    // ---- phase 5: v (packed), gate (packed), Wo accumulate (packed), store ----
#pragma unroll 1
    for (int r = 0; r < ROWS_PT; r++) {
        const int s = r * THREADS + tid;

        float2 xd[8];
#pragma unroll
        for (int j = 0; j < 8; j++) xd[j] = dup(x[r][j]);

        float v[8];
#pragma unroll
        for (int p = 0; p < 4; p++) {
            float2 a = mul2(xd[0], sWv2[p][0]);
#pragma unroll
            for (int j = 1; j < 8; j++) a = fma2(xd[j], sWv2[p][j], a);
            v[2 * p] = a.x; v[2 * p + 1] = a.y;
        }

        float w8[8];
#pragma unroll
        for (int h = 0; h < 8; h++) w8[h] = e[r][h] * sHrcp[h];

        float2 o2[4];
#pragma unroll
        for (int q = 0; q < 4; q++) o2[q] = make_float2(sBo[2 * q], sBo[2 * q + 1]);

#pragma unroll 4
        for (int p = 0; p < 32; p++) {           // idx pair (2p, 2p+1)
            float2 g2 = mul2(xd[0], sWg2[p][0]);
#pragma unroll
            for (int j = 1; j < 8; j++) g2 = fma2(xd[j], sWg2[p][j], g2);

            const float sig0 = __fdividef(1.f, 1.f + __expf(-g2.x));
            const float sig1 = __fdividef(1.f, 1.f + __expf(-g2.y));

            const int h  = p >> 2;
            const int c0 = (p & 3) * 2;
            const float wh = w8[h];
            const float2 cd0 = dup(sig0 * wh * v[c0]);
            const float2 cd1 = dup(sig1 * wh * v[c0 + 1]);

            const int idx0 = 2 * p;
#pragma unroll
            for (int q = 0; q < 4; q++) o2[q] = fma2(sWo2[idx0][q], cd0, o2[q]);
#pragma unroll
            for (int q = 0; q < 4; q++) o2[q] = fma2(sWo2[idx0 + 1][q], cd1, o2[q]);
        }

        float4* po = reinterpret_cast<float4*>(out + ((size_t)s * I_DIM + i) * 8);
        po[0] = make_float4(o2[0].x, o2[0].y, o2[1].x, o2[1].y);
        po[1] = make_float4(o2[2].x, o2[2].y, o2[3].x, o2[3].y);
    }
}

extern "C" void kernel_launch(void* const* d_in, const int* in_sizes, int n_in,
                              void* d_out, int out_size) {
    (void)in_sizes; (void)n_in; (void)out_size;
    const float* m        = (const float*)d_in[0];
    const float* ln_gamma = (const float*)d_in[1];
    const float* ln_beta  = (const float*)d_in[2];
    const float* Wq       = (const float*)d_in[3];
    const float* Wk       = (const float*)d_in[4];
    const float* Wv       = (const float*)d_in[5];
    const float* Wg       = (const float*)d_in[6];
    const float* Wo       = (const float*)d_in[7];
    const float* bo       = (const float*)d_in[8];
    float* out = (float*)d_out;

    msa_col_global_attn_kernel<<<I_DIM, THREADS>>>(
        m, ln_gamma, ln_beta, Wq, Wk, Wv, Wg, Wo, bo, out);
}

// round 3
// speedup vs baseline: 1.2228x; 1.1792x over previous
#include <cuda_runtime.h>
#include <math_constants.h>

// MSAColumnGlobalAttention: B=1, s=1024, i=512, c=8, h=8
// One CTA per column i. 512 threads, 2 rows per thread, rows processed JOINTLY
// so SMEM weights are loaded once (LDS.128) per idx-pair for both rows.
// k-projection folded into q: a[t,h] = x[t] . (Wk^T q[h]).

#define LN_EPS 1e-5f
#define S_DIM 1024
#define I_DIM 512
#define THREADS 512
#define NWARP (THREADS / 32)

__device__ __forceinline__ float2 fma2(float2 a, float2 b, float2 c) {
    unsigned long long ra = *reinterpret_cast<unsigned long long*>(&a);
    unsigned long long rb = *reinterpret_cast<unsigned long long*>(&b);
    unsigned long long rc = *reinterpret_cast<unsigned long long*>(&c);
    unsigned long long rd;
    asm("fma.rn.f32x2 %0, %1, %2, %3;" : "=l"(rd) : "l"(ra), "l"(rb), "l"(rc));
    return *reinterpret_cast<float2*>(&rd);
}
__device__ __forceinline__ float2 mul2(float2 a, float2 b) {
    unsigned long long ra = *reinterpret_cast<unsigned long long*>(&a);
    unsigned long long rb = *reinterpret_cast<unsigned long long*>(&b);
    unsigned long long rd;
    asm("mul.rn.f32x2 %0, %1, %2;" : "=l"(rd) : "l"(ra), "l"(rb));
    return *reinterpret_cast<float2*>(&rd);
}
__device__ __forceinline__ float2 dup(float x) { return make_float2(x, x); }
__device__ __forceinline__ float2 lo2(float4 w) { return make_float2(w.x, w.y); }
__device__ __forceinline__ float2 hi2(float4 w) { return make_float2(w.z, w.w); }

__device__ __forceinline__ float tanh_apx(float x) {
    float y; asm("tanh.approx.f32 %0, %1;" : "=f"(y) : "f"(x)); return y;
}
__device__ __forceinline__ float sig1(float g) {
    return fmaf(tanh_apx(g * 0.5f), 0.5f, 0.5f);
}

__device__ __forceinline__ float dot8(const float* x, const float* __restrict__ w) {
    float s = x[0] * w[0];
#pragma unroll
    for (int j = 1; j < 8; j++) s = fmaf(x[j], w[j], s);
    return s;
}

// accumulate pair-dot over 8 channels from 4 float4 weight words
#define PAIRDOT8(acc, xd, w0, w1, w2, w3)            \
    acc = mul2(xd[0], lo2(w0));                      \
    acc = fma2(xd[1], hi2(w0), acc);                 \
    acc = fma2(xd[2], lo2(w1), acc);                 \
    acc = fma2(xd[3], hi2(w1), acc);                 \
    acc = fma2(xd[4], lo2(w2), acc);                 \
    acc = fma2(xd[5], hi2(w2), acc);                 \
    acc = fma2(xd[6], lo2(w3), acc);                 \
    acc = fma2(xd[7], hi2(w3), acc);

__global__ __launch_bounds__(THREADS, 1)
void msa_col_global_attn_kernel(
    const float* __restrict__ m,
    const float* __restrict__ ln_gamma,
    const float* __restrict__ ln_beta,
    const float* __restrict__ Wq,    // (64, 8)
    const float* __restrict__ Wk,    // (8, 8)
    const float* __restrict__ Wv,    // (8, 8)
    const float* __restrict__ Wg,    // (64, 8)
    const float* __restrict__ Wo,    // (8, 64)
    const float* __restrict__ bo,    // (8,)
    float* __restrict__ out)
{
    const int i    = blockIdx.x;
    const int tid  = threadIdx.x;
    const int lane = tid & 31;
    const int warp = tid >> 5;

    // packed-pair weight tiles, read as float4
    __shared__ float4 sQK4[16];     // [hp*4+jj]: {qk[2hp][2jj], qk[2hp+1][2jj], qk[2hp][2jj+1], qk[2hp+1][2jj+1]}
    __shared__ float4 sWv4[16];     // same layout over c-pairs
    __shared__ float4 sWg4[128];    // [p*4+jj] over idx-pairs
    __shared__ float4 sWoF4[128];   // [idx*2+qq]: Wo[co][idx], co-contiguous
    __shared__ float  sWq[512];
    __shared__ float  sWkRaw[64];
    __shared__ float  sQraw[64];
    __shared__ float  sGamma[8], sBeta[8], sBo[8];
    __shared__ float  sRed[NWARP][8];
    __shared__ float  sXbar[8], sHmax[8], sHrcp[8];

    // ---- stage weights ----
    {
        float* g4 = reinterpret_cast<float*>(sWg4);
        float* o4 = reinterpret_cast<float*>(sWoF4);
        const int row = tid >> 3, j = tid & 7;
        sWq[tid] = Wq[tid];
        g4[(row >> 1) * 16 + (j >> 1) * 4 + (j & 1) * 2 + (row & 1)] = Wg[tid];
        const int co = tid >> 6, idx = tid & 63;
        o4[idx * 8 + co] = Wo[tid];
        if (tid < 64) {
            sWkRaw[tid] = Wk[tid];
            float* v4 = reinterpret_cast<float*>(sWv4);
            v4[(row >> 1) * 16 + (j >> 1) * 4 + (j & 1) * 2 + (row & 1)] = Wv[tid];
        }
        if (tid < 8) { sGamma[tid] = ln_gamma[tid]; sBeta[tid] = ln_beta[tid]; sBo[tid] = bo[tid]; }
    }
    __syncthreads();

    // ---- phase 1: load + LayerNorm (2 rows), accumulate column sum ----
    float x0[8], x1[8];
    float acc[8];
#pragma unroll
    for (int c = 0; c < 8; c++) acc[c] = 0.f;

#pragma unroll
    for (int r = 0; r < 2; r++) {
        float* xr_out = r ? x1 : x0;
        const int s = r * THREADS + tid;
        const float4* p = reinterpret_cast<const float4*>(m + ((size_t)s * I_DIM + i) * 8);
        float4 a0 = p[0];
        float4 a1 = p[1];
        float xr[8] = {a0.x, a0.y, a0.z, a0.w, a1.x, a1.y, a1.z, a1.w};
        float mean = 0.f;
#pragma unroll
        for (int c = 0; c < 8; c++) mean += xr[c];
        mean *= 0.125f;
        float var = 0.f;
#pragma unroll
        for (int c = 0; c < 8; c++) { float d = xr[c] - mean; var = fmaf(d, d, var); }
        var *= 0.125f;
        const float rstd = rsqrtf(var + LN_EPS);
#pragma unroll
        for (int c = 0; c < 8; c++) {
            float t = (xr[c] - mean) * rstd;
            t = fmaf(t, sGamma[c], sBeta[c]);
            xr_out[c] = t;
            acc[c] += t;
        }
    }

    // ---- reduce sum(x) -> xbar ----
#pragma unroll
    for (int c = 0; c < 8; c++) {
#pragma unroll
        for (int off = 16; off > 0; off >>= 1)
            acc[c] += __shfl_xor_sync(0xffffffffu, acc[c], off);
    }
    if (lane == 0) {
#pragma unroll
        for (int c = 0; c < 8; c++) sRed[warp][c] = acc[c];
    }
    __syncthreads();
    if (tid < 8) {
        float s = sRed[0][tid];
#pragma unroll
        for (int w = 1; w < NWARP; w++) s += sRed[w][tid];
        sXbar[tid] = s;
    }
    __syncthreads();

    // ---- q = xbar @ Wq.T (scaled), then fold Wk: qk[h][j] = sum_c q[h][c]*Wk[c][j] ----
    if (tid < 64) {
        const float qscale = (1.f / 1024.f) * 0.35355339059327373f;
        sQraw[tid] = dot8(sXbar, &sWq[tid * 8]) * qscale;
    }
    __syncthreads();
    if (tid < 64) {
        const int h = tid >> 3, j = tid & 7;
        float v = 0.f;
#pragma unroll
        for (int c = 0; c < 8; c++) v = fmaf(sQraw[h * 8 + c], sWkRaw[c * 8 + j], v);
        reinterpret_cast<float*>(sQK4)[(h >> 1) * 16 + (j >> 1) * 4 + (j & 1) * 2 + (h & 1)] = v;
    }
    __syncthreads();

    // ---- build duplicated x operands (once, reused in logits/v/gate) ----
    float2 xd0[8], xd1[8];
#pragma unroll
    for (int j = 0; j < 8; j++) { xd0[j] = dup(x0[j]); xd1[j] = dup(x1[j]); }

    // ---- logits: e[r][h] = x_r . qk[h], per-h max ----
    float e0[8], e1[8];
    float hred[8];
#pragma unroll
    for (int hp = 0; hp < 4; hp++) {
        const float4* qp = &sQK4[hp * 4];
        float4 w0 = qp[0], w1 = qp[1], w2 = qp[2], w3 = qp[3];
        float2 a0, a1;
        PAIRDOT8(a0, xd0, w0, w1, w2, w3);
        PAIRDOT8(a1, xd1, w0, w1, w2, w3);
        e0[2 * hp] = a0.x; e0[2 * hp + 1] = a0.y;
        e1[2 * hp] = a1.x; e1[2 * hp + 1] = a1.y;
        hred[2 * hp]     = fmaxf(a0.x, a1.x);
        hred[2 * hp + 1] = fmaxf(a0.y, a1.y);
    }

#pragma unroll
    for (int h = 0; h < 8; h++) {
#pragma unroll
        for (int off = 16; off > 0; off >>= 1)
            hred[h] = fmaxf(hred[h], __shfl_xor_sync(0xffffffffu, hred[h], off));
    }
    if (lane == 0) {
#pragma unroll
        for (int h = 0; h < 8; h++) sRed[warp][h] = hred[h];
    }
    __syncthreads();
    if (tid < 8) {
        float s = sRed[0][tid];
#pragma unroll
        for (int w = 1; w < NWARP; w++) s = fmaxf(s, sRed[w][tid]);
        sHmax[tid] = s;
    }
    __syncthreads();

    // ---- exp + per-h sum ----
#pragma unroll
    for (int h = 0; h < 8; h++) {
        e0[h] = __expf(e0[h] - sHmax[h]);
        e1[h] = __expf(e1[h] - sHmax[h]);
        hred[h] = e0[h] + e1[h];
    }
#pragma unroll
    for (int h = 0; h < 8; h++) {
#pragma unroll
        for (int off = 16; off > 0; off >>= 1)
            hred[h] += __shfl_xor_sync(0xffffffffu, hred[h], off);
    }
    if (lane == 0) {
#pragma unroll
        for (int h = 0; h < 8; h++) sRed[warp][h] = hred[h];
    }
    __syncthreads();
    if (tid < 8) {
        float s = sRed[0][tid];
#pragma unroll
        for (int w = 1; w < NWARP; w++) s += sRed[w][tid];
        sHrcp[tid] = __fdividef(1.f, s);
    }
    __syncthreads();

    // ---- softmax weights in-place ----
#pragma unroll
    for (int h = 0; h < 8; h++) {
        const float r = sHrcp[h];
        e0[h] *= r;
        e1[h] *= r;
    }

    // ---- v = x @ Wv.T (both rows) ----
    float v0[8], v1[8];
#pragma unroll
    for (int cp = 0; cp < 4; cp++) {
        const float4* vp = &sWv4[cp * 4];
        float4 w0 = vp[0], w1 = vp[1], w2 = vp[2], w3 = vp[3];
        float2 a0, a1;
        PAIRDOT8(a0, xd0, w0, w1, w2, w3);
        PAIRDOT8(a1, xd1, w0, w1, w2, w3);
        v0[2 * cp] = a0.x; v0[2 * cp + 1] = a0.y;
        v1[2 * cp] = a1.x; v1[2 * cp + 1] = a1.y;
    }

    // ---- gate + Wo accumulate, both rows jointly ----
    float2 o0[4], o1[4];
#pragma unroll
    for (int q = 0; q < 4; q++) {
        o0[q] = make_float2(sBo[2 * q], sBo[2 * q + 1]);
        o1[q] = o0[q];
    }

#pragma unroll 1
    for (int h = 0; h < 8; h++) {
        const float wh0 = e0[h], wh1 = e1[h];
#pragma unroll
        for (int pp = 0; pp < 4; pp++) {
            const int p = h * 4 + pp;
            const float4* gp = &sWg4[p * 4];
            float4 ga = gp[0], gb = gp[1], gc = gp[2], gd = gp[3];
            float2 g0, g1;
            PAIRDOT8(g0, xd0, ga, gb, gc, gd);
            PAIRDOT8(g1, xd1, ga, gb, gc, gd);

            const int c0 = pp * 2;
            const float2 cd00 = dup(sig1(g0.x) * wh0 * v0[c0]);
            const float2 cd01 = dup(sig1(g0.y) * wh0 * v0[c0 + 1]);
            const float2 cd10 = dup(sig1(g1.x) * wh1 * v1[c0]);
            const float2 cd11 = dup(sig1(g1.y) * wh1 * v1[c0 + 1]);

            const float4* wp = &sWoF4[p * 4];   // idx0=2p rows: [2p*2], [2p*2+1]; idx1: next two
            float4 u0 = wp[0], u1 = wp[1], u2 = wp[2], u3 = wp[3];

            o0[0] = fma2(lo2(u0), cd00, o0[0]);
            o0[1] = fma2(hi2(u0), cd00, o0[1]);
            o0[2] = fma2(lo2(u1), cd00, o0[2]);
            o0[3] = fma2(hi2(u1), cd00, o0[3]);
            o0[0] = fma2(lo2(u2), cd01, o0[0]);
            o0[1] = fma2(hi2(u2), cd01, o0[1]);
            o0[2] = fma2(lo2(u3), cd01, o0[2]);
            o0[3] = fma2(hi2(u3), cd01, o0[3]);

            o1[0] = fma2(lo2(u0), cd10, o1[0]);
            o1[1] = fma2(hi2(u0), cd10, o1[1]);
            o1[2] = fma2(lo2(u1), cd10, o1[2]);
            o1[3] = fma2(hi2(u1), cd10, o1[3]);
            o1[0] = fma2(lo2(u2), cd11, o1[0]);
            o1[1] = fma2(hi2(u2), cd11, o1[1]);
            o1[2] = fma2(lo2(u3), cd11, o1[2]);
            o1[3] = fma2(hi2(u3), cd11, o1[3]);
        }
    }

    // ---- store both rows ----
    {
        float4* po = reinterpret_cast<float4*>(out + ((size_t)tid * I_DIM + i) * 8);
        po[0] = make_float4(o0[0].x, o0[0].y, o0[1].x, o0[1].y);
        po[1] = make_float4(o0[2].x, o0[2].y, o0[3].x, o0[3].y);
        float4* po1 = reinterpret_cast<float4*>(out + ((size_t)(tid + THREADS) * I_DIM + i) * 8);
        po1[0] = make_float4(o1[0].x, o1[0].y, o1[1].x, o1[1].y);
        po1[1] = make_float4(o1[2].x, o1[2].y, o1[3].x, o1[3].y);
    }
}

extern "C" void kernel_launch(void* const* d_in, const int* in_sizes, int n_in,
                              void* d_out, int out_size) {
    (void)in_sizes; (void)n_in; (void)out_size;
    const float* m        = (const float*)d_in[0];
    const float* ln_gamma = (const float*)d_in[1];
    const float* ln_beta  = (const float*)d_in[2];
    const float* Wq       = (const float*)d_in[3];
    const float* Wk       = (const float*)d_in[4];
    const float* Wv       = (const float*)d_in[5];
    const float* Wg       = (const float*)d_in[6];
    const float* Wo       = (const float*)d_in[7];
    const float* bo       = (const float*)d_in[8];
    float* out = (float*)d_out;

    msa_col_global_attn_kernel<<<I_DIM, THREADS>>>(
        m, ln_gamma, ln_beta, Wq, Wk, Wv, Wg, Wo, bo, out);
}